// round 5
// baseline (speedup 1.0000x reference)
#include <cuda_runtime.h>

#define HW    16384
#define CCH   256
#define CHW   4194304   // 256*16384
#define NIMG  8

// g_acc layout (floats):
// [0,2048)      chS   = sum |S| per (n,c)
// [2048,4096)   chT
// [4096,6144)   SS2   = sum (S-T)^2
// [6144,8192)   SD    = sum (S-T)
// [8192,10240)  FG    = sum d^2 * eT * Mfg
// [10240,12288) BG    = sum d^2 * eT * bg_indicator
// [12288,14336) CXS   = sum S * exp(cmS)
// [14336,16384) CXT   = sum T * exp(cmT)
// [16384+n] ZfeaS  [16392+n] ZfeaT  [16400+n] ZcmS  [16408+n] ZcmT
// [16416+n] bgcnt  [16424] spatial L1
__device__ float g_acc[16432];
__device__ float g_Mfg[NIMG * HW];
__device__ float g_eS[NIMG * HW];
__device__ float g_eT[NIMG * HW];

__device__ __forceinline__ float warpSum(float v) {
#pragma unroll
    for (int o = 16; o; o >>= 1) v += __shfl_xor_sync(0xffffffffu, v, o);
    return v;
}

__global__ void zero_kernel() {
    int i = blockIdx.x * 256 + threadIdx.x;
    if (i < 16432) g_acc[i] = 0.f;
}

// ---------------- box-mask raster + bg count ----------------
__global__ void mask_kernel(const float* __restrict__ gt) {
    __shared__ float bx[100];  // wmin[20] wmax[20] hmin[20] hmax[20] area[20]
    int bid = blockIdx.x;
    int t = threadIdx.x;
    int n = bid >> 6;
    if (t < 20) {
        const float* g4 = gt + (size_t)(n * 20 + t) * 4;
        float wmin = floorf(g4[0] * 0.125f);   // x/1024*128, exact
        float hmin = floorf(g4[1] * 0.125f);
        float wmax = ceilf(g4[2] * 0.125f);
        float hmax = ceilf(g4[3] * 0.125f);
        bx[t]      = wmin;
        bx[20 + t] = wmax;
        bx[40 + t] = hmin;
        bx[60 + t] = hmax;
        bx[80 + t] = 1.f / ((hmax + 1.f - hmin) * (wmax + 1.f - wmin));
    }
    __syncthreads();
    int pix = (bid & 63) * 256 + t;
    float h = (float)(pix >> 7), w = (float)(pix & 127);
    float mf = 0.f;
#pragma unroll
    for (int b = 0; b < 20; ++b) {
        bool in = (h >= bx[40 + b]) && (h <= bx[60 + b]) &&
                  (w >= bx[b]) && (w <= bx[20 + b]);
        mf = fmaxf(mf, in ? bx[80 + b] : 0.f);
    }
    g_Mfg[n * HW + pix] = mf;
    unsigned bal = __ballot_sync(0xffffffffu, mf <= 0.f);
    if ((t & 31) == 0) atomicAdd(&g_acc[16416 + n], (float)__popc(bal));
}

// ---------------- main streaming pass ----------------
// grid: 256 blocks = 8 images x 32 blocks; each block: 512 pixels, all 256 ch.
// tile = 16 pixels x 256 channels staged in smem (pad 17).
#define SM_S   0        // 256*17 = 4352
#define SM_T   4352     // 4352
#define SM_WMS 8704     // 256
#define SM_WMT 8960     // 256
#define SM_WPX 9216     // 16 float4 = 64 floats (16B aligned: 9216*4 % 16 == 0)
#define SM_RED 9280     // 4 * 256
#define SM_TOT 10304    // 41216 bytes

__global__ __launch_bounds__(256) void main_kernel(
    const float* __restrict__ S, const float* __restrict__ T,
    const float* __restrict__ w_ms, const float* __restrict__ w_mt) {
    __shared__ __align__(16) float sm[SM_TOT];
    int t = threadIdx.x;
    int bid = blockIdx.x;
    int n = bid >> 5;
    int pixBase = (bid & 31) * 512;
    int g = t >> 4, p = t & 15;   // 16 channel-groups x 16 pixels
    sm[SM_WMS + t] = w_ms[t];
    sm[SM_WMT + t] = w_mt[t];
    float aChS = 0, aChT = 0, aSS2 = 0, aSD = 0, aFG = 0, aBG = 0, aCXS = 0, aCXT = 0;
    float zfS = 0, zfT = 0, zcS = 0, zcT = 0;   // only t<16 accumulate
    __syncthreads();

    for (int tile = 0; tile < 32; ++tile) {
        int pix0 = pixBase + tile * 16;
        const float* Sp = S + (size_t)n * CHW + (size_t)g * HW + pix0 + p;
        const float* Tp = T + (size_t)n * CHW + (size_t)g * HW + pix0 + p;
        float pabS = 0, pabT = 0, pcmS = 0, pcmT = 0;
#pragma unroll
        for (int it = 0; it < 16; ++it) {
            int c = it * 16 + g;
            float sv = __ldg(Sp), tv = __ldg(Tp);
            Sp += 16 * HW; Tp += 16 * HW;
            sm[SM_S + c * 17 + p] = sv;
            sm[SM_T + c * 17 + p] = tv;
            pabS += fabsf(sv); pabT += fabsf(tv);
            pcmS += sv * sm[SM_WMS + c];
            pcmT += tv * sm[SM_WMT + c];
        }
        sm[SM_RED +       t] = pabS;
        sm[SM_RED + 256 + t] = pabT;
        sm[SM_RED + 512 + t] = pcmS;
        sm[SM_RED + 768 + t] = pcmT;
        __syncthreads();
        if (t < 16) {
            float aS = 0, aT = 0, cS = 0, cT = 0;
#pragma unroll
            for (int gg = 0; gg < 16; ++gg) {
                aS += sm[SM_RED +       gg * 16 + t];
                aT += sm[SM_RED + 256 + gg * 16 + t];
                cS += sm[SM_RED + 512 + gg * 16 + t];
                cT += sm[SM_RED + 768 + gg * 16 + t];
            }
            // fea/TEMP = (sum/256)/0.5 = sum/128
            float eS  = __expf(aS * (1.f / 128.f));
            float eT  = __expf(aT * (1.f / 128.f));
            float ecS = __expf(cS);
            float ecT = __expf(cT);
            int pix = pix0 + t;
            float mf = g_Mfg[n * HW + pix];
            float bgi = (mf > 0.f) ? 0.f : 1.f;
            reinterpret_cast<float4*>(&sm[SM_WPX])[t] =
                make_float4(eT * mf, eT * bgi, ecS, ecT);
            g_eS[n * HW + pix] = eS;
            g_eT[n * HW + pix] = eT;
            zfS += eS; zfT += eT; zcS += ecS; zcT += ecT;
        }
        __syncthreads();
        // phase 2: thread t == channel t
        const float* srow = &sm[SM_S + t * 17];
        const float* trow = &sm[SM_T + t * 17];
        const float4* wpx = reinterpret_cast<const float4*>(&sm[SM_WPX]);
#pragma unroll
        for (int pp = 0; pp < 16; ++pp) {
            float4 wp = wpx[pp];
            float sv = srow[pp], tv = trow[pp];
            float d = sv - tv, d2 = d * d;
            aChS += fabsf(sv); aChT += fabsf(tv);
            aSS2 += d2;        aSD  += d;
            aFG  += d2 * wp.x; aBG  += d2 * wp.y;
            aCXS += sv * wp.z; aCXT += tv * wp.w;
        }
        __syncthreads();
    }
    int nc = n * CCH + t;
    atomicAdd(&g_acc[nc],          aChS);
    atomicAdd(&g_acc[2048  + nc],  aChT);
    atomicAdd(&g_acc[4096  + nc],  aSS2);
    atomicAdd(&g_acc[6144  + nc],  aSD);
    atomicAdd(&g_acc[8192  + nc],  aFG);
    atomicAdd(&g_acc[10240 + nc],  aBG);
    atomicAdd(&g_acc[12288 + nc],  aCXS);
    atomicAdd(&g_acc[14336 + nc],  aCXT);
    if (t < 32) {
        zfS = warpSum(zfS); zfT = warpSum(zfT);
        zcS = warpSum(zcS); zcT = warpSum(zcT);
        if (t == 0) {
            atomicAdd(&g_acc[16384 + n], zfS);
            atomicAdd(&g_acc[16392 + n], zfT);
            atomicAdd(&g_acc[16400 + n], zcS);
            atomicAdd(&g_acc[16408 + n], zcT);
        }
    }
}

// ---------------- spatial attention L1 ----------------
__global__ void spat_kernel() {
    int i = blockIdx.x * 256 + threadIdx.x;
    int n = i >> 14;
    float zs = g_acc[16384 + n], zt = g_acc[16392 + n];
    float v = fabsf(g_eS[i] * (16384.f / zs) - g_eT[i] * (16384.f / zt));
    v = warpSum(v);
    __shared__ float r[8];
    if ((threadIdx.x & 31) == 0) r[threadIdx.x >> 5] = v;
    __syncthreads();
    if (threadIdx.x < 32) {
        float x = (threadIdx.x < 8) ? r[threadIdx.x] : 0.f;
        x = warpSum(x);
        if (threadIdx.x == 0) atomicAdd(&g_acc[16424], x);
    }
}

// ---------------- epilogue: channel softmax, MLPs, combine ----------------
// warp w handles image n=w. outp may alias ctx (writes strictly after reads).
__device__ void channel_mlp(const float* __restrict__ ctx,   // smem [2048]
                            const float* __restrict__ w1, const float* __restrict__ b1,
                            const float* __restrict__ gam, const float* __restrict__ bet,
                            const float* __restrict__ w2, const float* __restrict__ b2,
                            float* __restrict__ yS,           // smem [1024]
                            float* __restrict__ outp) {       // smem [2048]
    int t = threadIdx.x, w = t >> 5, lane = t & 31;
    const float4* ctx4 = reinterpret_cast<const float4*>(ctx + w * 256);
    float acc[4];
#pragma unroll
    for (int k = 0; k < 4; ++k) acc[k] = b1[lane + 32 * k];
    for (int c4 = 0; c4 < 64; ++c4) {
        float4 cv = ctx4[c4];
#pragma unroll
        for (int k = 0; k < 4; ++k) {
            float4 wv = *reinterpret_cast<const float4*>(w1 + (size_t)(lane + 32 * k) * 256 + c4 * 4);
            acc[k] += cv.x * wv.x + cv.y * wv.y + cv.z * wv.z + cv.w * wv.w;
        }
    }
    float s = 0, s2 = 0;
#pragma unroll
    for (int k = 0; k < 4; ++k) { s += acc[k]; s2 += acc[k] * acc[k]; }
    s = warpSum(s); s2 = warpSum(s2);
    float mean = s * (1.f / 128.f);
    float var = s2 * (1.f / 128.f) - mean * mean;
    float inv = rsqrtf(var + 1e-5f);
#pragma unroll
    for (int k = 0; k < 4; ++k) {
        int j = lane + 32 * k;
        float y = (acc[k] - mean) * inv * gam[j] + bet[j];
        yS[w * 128 + j] = fmaxf(y, 0.f);
    }
    __syncwarp();
    const float4* y4 = reinterpret_cast<const float4*>(yS + w * 128);
    float o[8];
#pragma unroll
    for (int k = 0; k < 8; ++k) o[k] = b2[lane + 32 * k];
    for (int j4 = 0; j4 < 32; ++j4) {
        float4 yv = y4[j4];
#pragma unroll
        for (int k = 0; k < 8; ++k) {
            float4 wv = *reinterpret_cast<const float4*>(w2 + (size_t)(lane + 32 * k) * 128 + j4 * 4);
            o[k] += yv.x * wv.x + yv.y * wv.y + yv.z * wv.z + yv.w * wv.w;
        }
    }
    __syncwarp();
#pragma unroll
    for (int k = 0; k < 8; ++k) outp[w * 256 + lane + 32 * k] = o[k];
    __syncthreads();
}

__global__ __launch_bounds__(256) void final_kernel(
    const float* __restrict__ w1_s, const float* __restrict__ b1_s,
    const float* __restrict__ g_s,  const float* __restrict__ be_s,
    const float* __restrict__ w2_s, const float* __restrict__ b2_s,
    const float* __restrict__ w1_t, const float* __restrict__ b1_t,
    const float* __restrict__ g_t,  const float* __restrict__ be_t,
    const float* __restrict__ w2_t, const float* __restrict__ b2_t,
    float* __restrict__ out) {
    __shared__ __align__(16) float shFS[2048];
    __shared__ __align__(16) float shFT[2048];
    __shared__ __align__(16) float shCS[2048];   // ctx_s, then add_s
    __shared__ __align__(16) float shCT[2048];   // ctx_t, then add_t
    __shared__ __align__(16) float shY[1024];
    __shared__ float shZ[16];
    __shared__ float shR[8];
    int t = threadIdx.x, w = t >> 5, lane = t & 31;
#pragma unroll
    for (int n = 0; n < 8; ++n) {
        int i = n * 256 + t;
        // ch/TEMP = (sum/16384)/0.5 = sum/8192
        shFS[i] = __expf(g_acc[i]          * (1.f / 8192.f));
        shFT[i] = __expf(g_acc[2048 + i]   * (1.f / 8192.f));
        shCS[i] = g_acc[12288 + i] / g_acc[16400 + n];
        shCT[i] = g_acc[14336 + i] / g_acc[16408 + n];
    }
    __syncthreads();
    {   // per-image channel partition functions (warp w <-> image n=w)
        float zS = 0, zT = 0;
#pragma unroll
        for (int k = 0; k < 8; ++k) {
            int c = lane + 32 * k;
            zS += shFS[w * 256 + c];
            zT += shFT[w * 256 + c];
        }
        zS = warpSum(zS); zT = warpSum(zT);
        if (lane == 0) { shZ[w] = zS; shZ[8 + w] = zT; }
    }
    __syncthreads();
    channel_mlp(shCS, w1_s, b1_s, g_s, be_s, w2_s, b2_s, shY, shCS);  // -> add_s
    channel_mlp(shCT, w1_t, b1_t, g_t, be_t, w2_t, b2_t, shY, shCT);  // -> add_t

    float acc = 0.f;
#pragma unroll
    for (int n = 0; n < 8; ++n) {
        int i = n * 256 + t;
        float cS = 256.f * shFS[i] / shZ[n];
        float cT = 256.f * shFT[i] / shZ[8 + n];
        float wn = cT * (16384.f / g_acc[16392 + n]);
        float bgc = g_acc[16416 + n];
        float bgw = (bgc > 0.f) ? (1.f / bgc) : 0.f;
        float fg = wn * g_acc[8192 + i];
        float bg = wn * bgw * g_acc[10240 + i];
        float mC = fabsf(cS - cT);
        float delta = shCS[i] - shCT[i];
        float rel = g_acc[4096 + i] + 2.f * delta * g_acc[6144 + i]
                    + 16384.f * delta * delta;
        acc += 1e-3f * fg + 5e-4f * bg + 1e-3f * mC + 5e-6f * rel;
    }
    // block reduction
    acc = warpSum(acc);
    if (lane == 0) shR[w] = acc;
    __syncthreads();
    if (t < 32) {
        float x = (t < 8) ? shR[t] : 0.f;
        x = warpSum(x);
        if (t == 0) out[0] = (x + 1e-3f * g_acc[16424]) * 0.125f;
    }
}

extern "C" void kernel_launch(void* const* d_in, const int* in_sizes, int n_in,
                              void* d_out, int out_size) {
    const float* S    = (const float*)d_in[0];
    const float* T    = (const float*)d_in[1];
    const float* gt   = (const float*)d_in[2];
    const float* w_ms = (const float*)d_in[3];
    const float* w_mt = (const float*)d_in[5];
    const float* w1_s = (const float*)d_in[7];
    const float* b1_s = (const float*)d_in[8];
    const float* g_s  = (const float*)d_in[9];
    const float* be_s = (const float*)d_in[10];
    const float* w2_s = (const float*)d_in[11];
    const float* b2_s = (const float*)d_in[12];
    const float* w1_t = (const float*)d_in[13];
    const float* b1_t = (const float*)d_in[14];
    const float* g_t  = (const float*)d_in[15];
    const float* be_t = (const float*)d_in[16];
    const float* w2_t = (const float*)d_in[17];
    const float* b2_t = (const float*)d_in[18];

    zero_kernel<<<65, 256>>>();
    mask_kernel<<<512, 256>>>(gt);
    main_kernel<<<256, 256>>>(S, T, w_ms, w_mt);
    spat_kernel<<<512, 256>>>();
    final_kernel<<<1, 256>>>(w1_s, b1_s, g_s, be_s, w2_s, b2_s,
                             w1_t, b1_t, g_t, be_t, w2_t, b2_t,
                             (float*)d_out);
}

// round 6
// speedup vs baseline: 1.1960x; 1.1960x over previous
#include <cuda_runtime.h>

#define HW    16384
#define CCH   256
#define CHW   4194304   // 256*16384
#define NIMG  8

// g_acc layout (floats):
// [0,2048)      chS   = sum |S| per (n,c)
// [2048,4096)   chT
// [4096,6144)   SS2   = sum (S-T)^2
// [6144,8192)   SD    = sum (S-T)
// [8192,10240)  FG    = sum d^2 * eT * Mfg
// [10240,12288) BG    = sum d^2 * eT * bg_indicator
// [12288,14336) CXS   = sum S * exp(cmS)
// [14336,16384) CXT   = sum T * exp(cmT)
// [16384+n] ZfeaS  [16392+n] ZfeaT  [16400+n] ZcmS  [16408+n] ZcmT
// [16416+n] bgcnt  [16424] spatial L1
__device__ float g_acc[16432];
__device__ float g_Mfg[NIMG * HW];
__device__ float g_eS[NIMG * HW];
__device__ float g_eT[NIMG * HW];

__device__ __forceinline__ float warpSum(float v) {
#pragma unroll
    for (int o = 16; o; o >>= 1) v += __shfl_xor_sync(0xffffffffu, v, o);
    return v;
}

__global__ void zero_kernel() {
    int i = blockIdx.x * 256 + threadIdx.x;
    if (i < 16432) g_acc[i] = 0.f;
}

// ---------------- box-mask raster + bg count ----------------
__global__ void mask_kernel(const float* __restrict__ gt) {
    __shared__ float bx[100];  // wmin[20] wmax[20] hmin[20] hmax[20] area[20]
    int bid = blockIdx.x;
    int t = threadIdx.x;
    int n = bid >> 6;
    if (t < 20) {
        const float* g4 = gt + (size_t)(n * 20 + t) * 4;
        float wmin = floorf(g4[0] * 0.125f);   // x/1024*128, exact
        float hmin = floorf(g4[1] * 0.125f);
        float wmax = ceilf(g4[2] * 0.125f);
        float hmax = ceilf(g4[3] * 0.125f);
        bx[t]      = wmin;
        bx[20 + t] = wmax;
        bx[40 + t] = hmin;
        bx[60 + t] = hmax;
        bx[80 + t] = 1.f / ((hmax + 1.f - hmin) * (wmax + 1.f - wmin));
    }
    __syncthreads();
    int pix = (bid & 63) * 256 + t;
    float h = (float)(pix >> 7), w = (float)(pix & 127);
    float mf = 0.f;
#pragma unroll
    for (int b = 0; b < 20; ++b) {
        bool in = (h >= bx[40 + b]) && (h <= bx[60 + b]) &&
                  (w >= bx[b]) && (w <= bx[20 + b]);
        mf = fmaxf(mf, in ? bx[80 + b] : 0.f);
    }
    g_Mfg[n * HW + pix] = mf;
    unsigned bal = __ballot_sync(0xffffffffu, mf <= 0.f);
    if ((t & 31) == 0) atomicAdd(&g_acc[16416 + n], (float)__popc(bal));
}

// ---------------- main streaming pass (pipelined) ----------------
// grid: 1024 blocks = 8 images x 128 blocks; each block: 128 pixels, 8 tiles
// of 16 pixels x 256 channels staged in smem (pad 17).
// thread t: g = t>>4 selects 16-channel slab [g*16, g*16+16), p = t&15 pixel.
#define SM_S   0        // 256*17 = 4352
#define SM_T   4352     // 4352
#define SM_WMS 8704     // 256
#define SM_WMT 8960     // 256
#define SM_WPX 9216     // 16 float4 = 64 floats
#define SM_RED 9280     // 4 * 256
#define SM_TOT 10304    // 41216 bytes

__global__ __launch_bounds__(256) void main_kernel(
    const float* __restrict__ S, const float* __restrict__ T,
    const float* __restrict__ w_ms, const float* __restrict__ w_mt) {
    __shared__ __align__(16) float sm[SM_TOT];
    int t = threadIdx.x;
    int bid = blockIdx.x;
    int n = bid >> 7;
    int pixBase = (bid & 127) * 128;
    int g = t >> 4, p = t & 15;
    int gBase = g * 16;                    // first channel of this thread's slab
    const float* Sp = S + (size_t)n * CHW + (size_t)gBase * HW + pixBase + p;
    const float* Tp = T + (size_t)n * CHW + (size_t)gBase * HW + pixBase + p;

    float rS[16], rT[16];
#pragma unroll
    for (int it = 0; it < 16; ++it) {      // prefetch tile 0 (issued first)
        rS[it] = __ldg(Sp + (size_t)it * HW);
        rT[it] = __ldg(Tp + (size_t)it * HW);
    }
    sm[SM_WMS + t] = w_ms[t];
    sm[SM_WMT + t] = w_mt[t];
    float aChS = 0, aChT = 0, aSS2 = 0, aSD = 0, aFG = 0, aBG = 0, aCXS = 0, aCXT = 0;
    float zfS = 0, zfT = 0, zcS = 0, zcT = 0;   // only t<16 accumulate
    __syncthreads();

    for (int tile = 0; tile < 8; ++tile) {
        int pix0 = pixBase + tile * 16;
        bool pf = (tile < 7);
        int nxt = tile * 16 + 16;          // relative pixel offset of next tile
        float pabS = 0, pabT = 0, pcmS = 0, pcmT = 0;
#pragma unroll
        for (int it = 0; it < 16; ++it) {
            int c = gBase + it;
            float sv = rS[it], tv = rT[it];
            sm[SM_S + c * 17 + p] = sv;
            sm[SM_T + c * 17 + p] = tv;
            pabS += fabsf(sv); pabT += fabsf(tv);
            pcmS += sv * sm[SM_WMS + c];
            pcmT += tv * sm[SM_WMT + c];
            if (pf) {                      // prefetch next tile, overlaps phase 2
                rS[it] = __ldg(Sp + (size_t)it * HW + nxt);
                rT[it] = __ldg(Tp + (size_t)it * HW + nxt);
            }
        }
        sm[SM_RED +       t] = pabS;
        sm[SM_RED + 256 + t] = pabT;
        sm[SM_RED + 512 + t] = pcmS;
        sm[SM_RED + 768 + t] = pcmT;
        __syncthreads();
        if (t < 16) {
            float aS = 0, aT = 0, cS = 0, cT = 0;
#pragma unroll
            for (int gg = 0; gg < 16; ++gg) {
                aS += sm[SM_RED +       gg * 16 + t];
                aT += sm[SM_RED + 256 + gg * 16 + t];
                cS += sm[SM_RED + 512 + gg * 16 + t];
                cT += sm[SM_RED + 768 + gg * 16 + t];
            }
            // fea/TEMP = (sum/256)/0.5 = sum/128
            float eS  = __expf(aS * (1.f / 128.f));
            float eT  = __expf(aT * (1.f / 128.f));
            float ecS = __expf(cS);
            float ecT = __expf(cT);
            int pix = pix0 + t;
            float mf = g_Mfg[n * HW + pix];
            float bgi = (mf > 0.f) ? 0.f : 1.f;
            reinterpret_cast<float4*>(&sm[SM_WPX])[t] =
                make_float4(eT * mf, eT * bgi, ecS, ecT);
            g_eS[n * HW + pix] = eS;
            g_eT[n * HW + pix] = eT;
            zfS += eS; zfT += eT; zcS += ecS; zcT += ecT;
        }
        __syncthreads();
        // phase 2: thread t == channel t
        const float* srow = &sm[SM_S + t * 17];
        const float* trow = &sm[SM_T + t * 17];
        const float4* wpx = reinterpret_cast<const float4*>(&sm[SM_WPX]);
#pragma unroll
        for (int pp = 0; pp < 16; ++pp) {
            float4 wp = wpx[pp];
            float sv = srow[pp], tv = trow[pp];
            float d = sv - tv, d2 = d * d;
            aChS += fabsf(sv); aChT += fabsf(tv);
            aSS2 += d2;        aSD  += d;
            aFG  += d2 * wp.x; aBG  += d2 * wp.y;
            aCXS += sv * wp.z; aCXT += tv * wp.w;
        }
        __syncthreads();
    }
    int nc = n * CCH + t;
    atomicAdd(&g_acc[nc],          aChS);
    atomicAdd(&g_acc[2048  + nc],  aChT);
    atomicAdd(&g_acc[4096  + nc],  aSS2);
    atomicAdd(&g_acc[6144  + nc],  aSD);
    atomicAdd(&g_acc[8192  + nc],  aFG);
    atomicAdd(&g_acc[10240 + nc],  aBG);
    atomicAdd(&g_acc[12288 + nc],  aCXS);
    atomicAdd(&g_acc[14336 + nc],  aCXT);
    if (t < 32) {
        zfS = warpSum(zfS); zfT = warpSum(zfT);
        zcS = warpSum(zcS); zcT = warpSum(zcT);
        if (t == 0) {
            atomicAdd(&g_acc[16384 + n], zfS);
            atomicAdd(&g_acc[16392 + n], zfT);
            atomicAdd(&g_acc[16400 + n], zcS);
            atomicAdd(&g_acc[16408 + n], zcT);
        }
    }
}

// ---------------- spatial attention L1 ----------------
__global__ void spat_kernel() {
    int i = blockIdx.x * 256 + threadIdx.x;
    int n = i >> 14;
    float zs = g_acc[16384 + n], zt = g_acc[16392 + n];
    float v = fabsf(g_eS[i] * (16384.f / zs) - g_eT[i] * (16384.f / zt));
    v = warpSum(v);
    __shared__ float r[8];
    if ((threadIdx.x & 31) == 0) r[threadIdx.x >> 5] = v;
    __syncthreads();
    if (threadIdx.x < 32) {
        float x = (threadIdx.x < 8) ? r[threadIdx.x] : 0.f;
        x = warpSum(x);
        if (threadIdx.x == 0) atomicAdd(&g_acc[16424], x);
    }
}

// ---------------- epilogue: channel softmax, MLPs, combine ----------------
// warp w handles image n=w. outp may alias ctx (writes strictly after reads).
__device__ void channel_mlp(const float* __restrict__ ctx,   // smem [2048]
                            const float* __restrict__ w1, const float* __restrict__ b1,
                            const float* __restrict__ gam, const float* __restrict__ bet,
                            const float* __restrict__ w2, const float* __restrict__ b2,
                            float* __restrict__ yS,           // smem [1024]
                            float* __restrict__ outp) {       // smem [2048]
    int t = threadIdx.x, w = t >> 5, lane = t & 31;
    const float4* ctx4 = reinterpret_cast<const float4*>(ctx + w * 256);
    float acc[4];
#pragma unroll
    for (int k = 0; k < 4; ++k) acc[k] = b1[lane + 32 * k];
    for (int c4 = 0; c4 < 64; ++c4) {
        float4 cv = ctx4[c4];
#pragma unroll
        for (int k = 0; k < 4; ++k) {
            float4 wv = *reinterpret_cast<const float4*>(w1 + (size_t)(lane + 32 * k) * 256 + c4 * 4);
            acc[k] += cv.x * wv.x + cv.y * wv.y + cv.z * wv.z + cv.w * wv.w;
        }
    }
    float s = 0, s2 = 0;
#pragma unroll
    for (int k = 0; k < 4; ++k) { s += acc[k]; s2 += acc[k] * acc[k]; }
    s = warpSum(s); s2 = warpSum(s2);
    float mean = s * (1.f / 128.f);
    float var = s2 * (1.f / 128.f) - mean * mean;
    float inv = rsqrtf(var + 1e-5f);
#pragma unroll
    for (int k = 0; k < 4; ++k) {
        int j = lane + 32 * k;
        float y = (acc[k] - mean) * inv * gam[j] + bet[j];
        yS[w * 128 + j] = fmaxf(y, 0.f);
    }
    __syncwarp();
    const float4* y4 = reinterpret_cast<const float4*>(yS + w * 128);
    float o[8];
#pragma unroll
    for (int k = 0; k < 8; ++k) o[k] = b2[lane + 32 * k];
    for (int j4 = 0; j4 < 32; ++j4) {
        float4 yv = y4[j4];
#pragma unroll
        for (int k = 0; k < 8; ++k) {
            float4 wv = *reinterpret_cast<const float4*>(w2 + (size_t)(lane + 32 * k) * 128 + j4 * 4);
            o[k] += yv.x * wv.x + yv.y * wv.y + yv.z * wv.z + yv.w * wv.w;
        }
    }
    __syncwarp();
#pragma unroll
    for (int k = 0; k < 8; ++k) outp[w * 256 + lane + 32 * k] = o[k];
    __syncthreads();
}

__global__ __launch_bounds__(256) void final_kernel(
    const float* __restrict__ w1_s, const float* __restrict__ b1_s,
    const float* __restrict__ g_s,  const float* __restrict__ be_s,
    const float* __restrict__ w2_s, const float* __restrict__ b2_s,
    const float* __restrict__ w1_t, const float* __restrict__ b1_t,
    const float* __restrict__ g_t,  const float* __restrict__ be_t,
    const float* __restrict__ w2_t, const float* __restrict__ b2_t,
    float* __restrict__ out) {
    __shared__ __align__(16) float shFS[2048];
    __shared__ __align__(16) float shFT[2048];
    __shared__ __align__(16) float shCS[2048];   // ctx_s, then add_s
    __shared__ __align__(16) float shCT[2048];   // ctx_t, then add_t
    __shared__ __align__(16) float shY[1024];
    __shared__ float shZ[16];
    __shared__ float shR[8];
    int t = threadIdx.x, w = t >> 5, lane = t & 31;
#pragma unroll
    for (int n = 0; n < 8; ++n) {
        int i = n * 256 + t;
        // ch/TEMP = (sum/16384)/0.5 = sum/8192
        shFS[i] = __expf(g_acc[i]          * (1.f / 8192.f));
        shFT[i] = __expf(g_acc[2048 + i]   * (1.f / 8192.f));
        shCS[i] = g_acc[12288 + i] / g_acc[16400 + n];
        shCT[i] = g_acc[14336 + i] / g_acc[16408 + n];
    }
    __syncthreads();
    {   // per-image channel partition functions (warp w <-> image n=w)
        float zS = 0, zT = 0;
#pragma unroll
        for (int k = 0; k < 8; ++k) {
            int c = lane + 32 * k;
            zS += shFS[w * 256 + c];
            zT += shFT[w * 256 + c];
        }
        zS = warpSum(zS); zT = warpSum(zT);
        if (lane == 0) { shZ[w] = zS; shZ[8 + w] = zT; }
    }
    __syncthreads();
    channel_mlp(shCS, w1_s, b1_s, g_s, be_s, w2_s, b2_s, shY, shCS);  // -> add_s
    channel_mlp(shCT, w1_t, b1_t, g_t, be_t, w2_t, b2_t, shY, shCT);  // -> add_t

    float acc = 0.f;
#pragma unroll
    for (int n = 0; n < 8; ++n) {
        int i = n * 256 + t;
        float cS = 256.f * shFS[i] / shZ[n];
        float cT = 256.f * shFT[i] / shZ[8 + n];
        float wn = cT * (16384.f / g_acc[16392 + n]);
        float bgc = g_acc[16416 + n];
        float bgw = (bgc > 0.f) ? (1.f / bgc) : 0.f;
        float fg = wn * g_acc[8192 + i];
        float bg = wn * bgw * g_acc[10240 + i];
        float mC = fabsf(cS - cT);
        float delta = shCS[i] - shCT[i];
        float rel = g_acc[4096 + i] + 2.f * delta * g_acc[6144 + i]
                    + 16384.f * delta * delta;
        acc += 1e-3f * fg + 5e-4f * bg + 1e-3f * mC + 5e-6f * rel;
    }
    // block reduction
    acc = warpSum(acc);
    if (lane == 0) shR[w] = acc;
    __syncthreads();
    if (t < 32) {
        float x = (t < 8) ? shR[t] : 0.f;
        x = warpSum(x);
        if (t == 0) out[0] = (x + 1e-3f * g_acc[16424]) * 0.125f;
    }
}

extern "C" void kernel_launch(void* const* d_in, const int* in_sizes, int n_in,
                              void* d_out, int out_size) {
    const float* S    = (const float*)d_in[0];
    const float* T    = (const float*)d_in[1];
    const float* gt   = (const float*)d_in[2];
    const float* w_ms = (const float*)d_in[3];
    const float* w_mt = (const float*)d_in[5];
    const float* w1_s = (const float*)d_in[7];
    const float* b1_s = (const float*)d_in[8];
    const float* g_s  = (const float*)d_in[9];
    const float* be_s = (const float*)d_in[10];
    const float* w2_s = (const float*)d_in[11];
    const float* b2_s = (const float*)d_in[12];
    const float* w1_t = (const float*)d_in[13];
    const float* b1_t = (const float*)d_in[14];
    const float* g_t  = (const float*)d_in[15];
    const float* be_t = (const float*)d_in[16];
    const float* w2_t = (const float*)d_in[17];
    const float* b2_t = (const float*)d_in[18];

    zero_kernel<<<65, 256>>>();
    mask_kernel<<<512, 256>>>(gt);
    main_kernel<<<1024, 256>>>(S, T, w_ms, w_mt);
    spat_kernel<<<512, 256>>>();
    final_kernel<<<1, 256>>>(w1_s, b1_s, g_s, be_s, w2_s, b2_s,
                             w1_t, b1_t, g_t, be_t, w2_t, b2_t,
                             (float*)d_out);
}